// round 3
// baseline (speedup 1.0000x reference)
#include <cuda_runtime.h>
#include <math.h>

#define BB 256
#define TT 512
#define KK 256

typedef unsigned long long ull;

// scratch for xU [B*T, K] = 134MB (static device global: no runtime alloc)
__device__ float g_xu[(size_t)BB * TT * KK];

#define FMA2(d, a, b) \
    asm("fma.rn.f32x2 %0, %1, %2, %0;" : "+l"(d) : "l"(a), "l"(b))
#define UNPK(x, y, v) \
    asm("mov.b64 {%0, %1}, %2;" : "=f"(x), "=f"(y) : "l"(v))

// ---------------------------------------------------------------------------
// Phase 1: C[m][n] = sum_d A[m][d] * U[d][n],  M=131072, N=K=256
// CTA tile 128x128, 256 threads, 8x8 microtile via packed f32x2.
// A tile duplicated in smem so {a,a} splats load as single 64-bit words.
// ---------------------------------------------------------------------------
__global__ __launch_bounds__(256) void xu_gemm(const float* __restrict__ A,
                                               const float* __restrict__ U) {
    __shared__ float Asd[16][256];  // [k][2r],[2r+1] both hold A[m0+r][kc+k]
    __shared__ float Bs[16][128];   // [k][n]

    const int tid = threadIdx.x;
    const int m0 = (blockIdx.x >> 1) * 128;
    const int n0 = (blockIdx.x & 1) * 128;
    const int tx = tid & 15;   // cols tx*8 .. +7
    const int ty = tid >> 4;   // rows ty*8 .. +7

    ull acc[8][4];
#pragma unroll
    for (int i = 0; i < 8; i++)
#pragma unroll
        for (int j = 0; j < 4; j++) acc[i][j] = 0ull;

    for (int kc = 0; kc < 256; kc += 16) {
#pragma unroll
        for (int l = 0; l < 2; l++) {
            int idx = tid * 2 + l;        // 0..511
            int r   = idx >> 2;           // row 0..127
            int kq  = (idx & 3) * 4;      // k 0,4,8,12
            const float4 f = *reinterpret_cast<const float4*>(
                &A[(size_t)(m0 + r) * 256 + kc + kq]);
            *reinterpret_cast<float2*>(&Asd[kq + 0][2 * r]) = make_float2(f.x, f.x);
            *reinterpret_cast<float2*>(&Asd[kq + 1][2 * r]) = make_float2(f.y, f.y);
            *reinterpret_cast<float2*>(&Asd[kq + 2][2 * r]) = make_float2(f.z, f.z);
            *reinterpret_cast<float2*>(&Asd[kq + 3][2 * r]) = make_float2(f.w, f.w);
        }
#pragma unroll
        for (int l = 0; l < 2; l++) {
            int idx = tid * 2 + l;        // 0..511
            int r   = idx >> 5;           // 0..15
            int cg  = (idx & 31) * 4;
            *reinterpret_cast<float4*>(&Bs[r][cg]) =
                *reinterpret_cast<const float4*>(&U[(size_t)(kc + r) * 256 + n0 + cg]);
        }
        __syncthreads();

#pragma unroll
        for (int k = 0; k < 16; k++) {
            ulonglong2 A01 = *reinterpret_cast<ulonglong2*>(&Asd[k][ty * 16 + 0]);
            ulonglong2 A23 = *reinterpret_cast<ulonglong2*>(&Asd[k][ty * 16 + 4]);
            ulonglong2 A45 = *reinterpret_cast<ulonglong2*>(&Asd[k][ty * 16 + 8]);
            ulonglong2 A67 = *reinterpret_cast<ulonglong2*>(&Asd[k][ty * 16 + 12]);
            ulonglong2 B01 = *reinterpret_cast<ulonglong2*>(&Bs[k][tx * 8 + 0]);
            ulonglong2 B23 = *reinterpret_cast<ulonglong2*>(&Bs[k][tx * 8 + 4]);
            ull ad[8] = {A01.x, A01.y, A23.x, A23.y, A45.x, A45.y, A67.x, A67.y};
            ull bp[4] = {B01.x, B01.y, B23.x, B23.y};
#pragma unroll
            for (int i = 0; i < 8; i++)
#pragma unroll
                for (int j = 0; j < 4; j++) FMA2(acc[i][j], ad[i], bp[j]);
        }
        __syncthreads();
    }

#pragma unroll
    for (int i = 0; i < 8; i++) {
        float* Crow = &g_xu[(size_t)(m0 + ty * 8 + i) * 256 + n0 + tx * 8];
        float v0, v1, v2, v3, v4, v5, v6, v7;
        UNPK(v0, v1, acc[i][0]);
        UNPK(v2, v3, acc[i][1]);
        UNPK(v4, v5, acc[i][2]);
        UNPK(v6, v7, acc[i][3]);
        *reinterpret_cast<float4*>(Crow + 0) = make_float4(v0, v1, v2, v3);
        *reinterpret_cast<float4*>(Crow + 4) = make_float4(v4, v5, v6, v7);
    }
}

// ---------------------------------------------------------------------------
// Phase 2: persistent batch-parallel recurrence. 128 CTAs x 2 batch rows.
// Thread (c = tid&127, kh = tid>>7): cols {2c,2c+1}, K-half kh.
// W: rows k in [kh*128, kh*128+64) in smem (128KB total);
//    rows k in [kh*128+64, kh*128+128) register-resident (wt[64], per-col-pair).
// h double-buffered in smem as {h0,h0,h1,h1} float4 per k (splat-ready).
// ---------------------------------------------------------------------------
__global__ __launch_bounds__(256, 1) void rnn_scan(const float* __restrict__ Wg,
                                                   const float* __restrict__ bg,
                                                   float* __restrict__ out) {
    extern __shared__ float smem[];
    float*  Ws   = smem;                                       // 128*256 floats (128KB)
    float4* hb4  = reinterpret_cast<float4*>(smem + 32768);    // 2 x 256 float4 (8KB)
    ull*    redu = reinterpret_cast<ull*>(smem + 32768 + 2048);// 256 ull (2KB)

    const int tid = threadIdx.x;
    const int c   = tid & 127;
    const int cc  = 2 * c;
    const int kh  = tid >> 7;
    const int b0  = blockIdx.x * 2;
    const int b1  = b0 + 1;

    // cooperative load of smem W rows: smem row s<64 <- k=s ; s>=64 <- k=s+64
    for (int i = tid; i < 128 * 64; i += 256) {
        int dr = i >> 6;
        int cw = (i & 63) << 2;
        int sr = dr < 64 ? dr : dr + 64;
        *reinterpret_cast<float4*>(&Ws[dr * 256 + cw]) =
            *reinterpret_cast<const float4*>(&Wg[(size_t)sr * 256 + cw]);
    }
    // register-resident W tail for this thread's column pair
    ull wt[64];
    {
        const int kb = kh * 128 + 64;
#pragma unroll
        for (int j = 0; j < 64; j++)
            wt[j] = *reinterpret_cast<const ull*>(&Wg[(size_t)(kb + j) * 256 + cc]);
    }
    // zero both h buffers
    for (int i = tid; i < 512; i += 256) hb4[i] = make_float4(0.f, 0.f, 0.f, 0.f);

    float2 bc   = make_float2(0.f, 0.f);
    float2 cur0 = make_float2(0.f, 0.f), cur1 = make_float2(0.f, 0.f);
    const float* xp0 = &g_xu[((size_t)b0 * TT) * 256 + cc];
    const float* xp1 = &g_xu[((size_t)b1 * TT) * 256 + cc];
    if (kh == 0) {
        bc   = *reinterpret_cast<const float2*>(&bg[cc]);
        cur0 = *reinterpret_cast<const float2*>(xp0);
        cur1 = *reinterpret_cast<const float2*>(xp1);
    }
    __syncthreads();

    int rb = 0;
    const int khbase = kh * 64;
    for (int t = 0; t < TT; t++) {
        // prefetch next step's xu (overlaps with the FMA chain below)
        float2 nxt0 = cur0, nxt1 = cur1;
        if (kh == 0 && t + 1 < TT) {
            nxt0 = *reinterpret_cast<const float2*>(xp0 + (size_t)(t + 1) * 256);
            nxt1 = *reinterpret_cast<const float2*>(xp1 + (size_t)(t + 1) * 256);
        }

        const ulonglong2* hp =
            reinterpret_cast<const ulonglong2*>(hb4 + rb * 256 + kh * 128);
        ull a0 = 0ull, a1 = 0ull;
#pragma unroll 8
        for (int j = 0; j < 64; j++) {
            ulonglong2 h2 = hp[j];  // {h0,h0},{h1,h1} broadcast
            ull w = *reinterpret_cast<const ull*>(&Ws[(khbase + j) * 256 + cc]);
            FMA2(a0, h2.x, w);
            FMA2(a1, h2.y, w);
        }
#pragma unroll 8
        for (int j = 0; j < 64; j++) {
            ulonglong2 h2 = hp[64 + j];
            FMA2(a0, h2.x, wt[j]);
            FMA2(a1, h2.y, wt[j]);
        }

        if (kh == 1) {
            redu[cc]     = a0;
            redu[cc + 1] = a1;
        }
        __syncthreads();
        if (kh == 0) {
            float s0x, s0y, s1x, s1y, p0x, p0y, p1x, p1y;
            UNPK(s0x, s0y, a0);
            UNPK(s1x, s1y, a1);
            UNPK(p0x, p0y, redu[cc]);
            UNPK(p1x, p1y, redu[cc + 1]);
            float r0x = tanhf(s0x + p0x + cur0.x + bc.x);
            float r0y = tanhf(s0y + p0y + cur0.y + bc.y);
            float r1x = tanhf(s1x + p1x + cur1.x + bc.x);
            float r1y = tanhf(s1y + p1y + cur1.y + bc.y);
            float4* hw = hb4 + (1 - rb) * 256;
            hw[cc]     = make_float4(r0x, r0x, r1x, r1x);
            hw[cc + 1] = make_float4(r0y, r0y, r1y, r1y);
        }
        __syncthreads();
        cur0 = nxt0;
        cur1 = nxt1;
        rb ^= 1;
    }

    // final h is in buffer rb (512 toggles -> rb==0, last write went to buf 0)
    if (kh == 0) {
        float4 p = hb4[rb * 256 + cc];      // {h0[2c],h0,h1[2c],h1}
        float4 q = hb4[rb * 256 + cc + 1];  // {h0[2c+1],...}
        *reinterpret_cast<float2*>(&out[(size_t)b0 * 256 + cc]) = make_float2(p.x, q.x);
        *reinterpret_cast<float2*>(&out[(size_t)b1 * 256 + cc]) = make_float2(p.z, q.z);
    }
}

extern "C" void kernel_launch(void* const* d_in, const int* in_sizes, int n_in,
                              void* d_out, int out_size) {
    const float* inputs = (const float*)d_in[0];  // [B,T,D]
    const float* U      = (const float*)d_in[1];  // [D,K]
    const float* W      = (const float*)d_in[2];  // [K,K]
    const float* b      = (const float*)d_in[3];  // [K]
    float* out          = (float*)d_out;          // [B,1,K]

    xu_gemm<<<2048, 256>>>(inputs, U);

    const int smem_bytes = 141312;  // 128KB W + 8KB h + 2KB red
    cudaFuncSetAttribute(rnn_scan, cudaFuncAttributeMaxDynamicSharedMemorySize,
                         smem_bytes);
    rnn_scan<<<128, 256, smem_bytes>>>(W, b, out);
}

// round 5
// speedup vs baseline: 1.1954x; 1.1954x over previous
#include <cuda_runtime.h>
#include <math.h>

#define BB 256
#define TT 512
#define KK 256

typedef unsigned long long ull;

// scratch for xU [B*T, K] = 134MB (static device global: no runtime alloc)
__device__ float g_xu[(size_t)BB * TT * KK];

#define FMA2(d, a, b) \
    asm("fma.rn.f32x2 %0, %1, %2, %0;" : "+l"(d) : "l"(a), "l"(b))
#define UNPK(x, y, v) \
    asm("mov.b64 {%0, %1}, %2;" : "=f"(x), "=f"(y) : "l"(v))

// ---------------------------------------------------------------------------
// Phase 1: C[m][n] = sum_d A[m][d] * U[d][n],  M=131072, N=K=256
// CTA tile 128x128, 256 threads, 8x8 microtile via packed f32x2.
// A tile duplicated in smem so {a,a} splats load as single 64-bit words.
// ---------------------------------------------------------------------------
__global__ __launch_bounds__(256) void xu_gemm(const float* __restrict__ A,
                                               const float* __restrict__ U) {
    __shared__ float Asd[16][256];  // [k][2r],[2r+1] both hold A[m0+r][kc+k]
    __shared__ float Bs[16][128];   // [k][n]

    const int tid = threadIdx.x;
    const int m0 = (blockIdx.x >> 1) * 128;
    const int n0 = (blockIdx.x & 1) * 128;
    const int tx = tid & 15;   // cols tx*8 .. +7
    const int ty = tid >> 4;   // rows ty*8 .. +7

    ull acc[8][4];
#pragma unroll
    for (int i = 0; i < 8; i++)
#pragma unroll
        for (int j = 0; j < 4; j++) acc[i][j] = 0ull;

    for (int kc = 0; kc < 256; kc += 16) {
#pragma unroll
        for (int l = 0; l < 2; l++) {
            int idx = tid * 2 + l;        // 0..511
            int r   = idx >> 2;           // row 0..127
            int kq  = (idx & 3) * 4;      // k 0,4,8,12
            const float4 f = *reinterpret_cast<const float4*>(
                &A[(size_t)(m0 + r) * 256 + kc + kq]);
            *reinterpret_cast<float2*>(&Asd[kq + 0][2 * r]) = make_float2(f.x, f.x);
            *reinterpret_cast<float2*>(&Asd[kq + 1][2 * r]) = make_float2(f.y, f.y);
            *reinterpret_cast<float2*>(&Asd[kq + 2][2 * r]) = make_float2(f.z, f.z);
            *reinterpret_cast<float2*>(&Asd[kq + 3][2 * r]) = make_float2(f.w, f.w);
        }
#pragma unroll
        for (int l = 0; l < 2; l++) {
            int idx = tid * 2 + l;        // 0..511
            int r   = idx >> 5;           // 0..15
            int cg  = (idx & 31) * 4;
            *reinterpret_cast<float4*>(&Bs[r][cg]) =
                *reinterpret_cast<const float4*>(&U[(size_t)(kc + r) * 256 + n0 + cg]);
        }
        __syncthreads();

#pragma unroll
        for (int k = 0; k < 16; k++) {
            ulonglong2 A01 = *reinterpret_cast<ulonglong2*>(&Asd[k][ty * 16 + 0]);
            ulonglong2 A23 = *reinterpret_cast<ulonglong2*>(&Asd[k][ty * 16 + 4]);
            ulonglong2 A45 = *reinterpret_cast<ulonglong2*>(&Asd[k][ty * 16 + 8]);
            ulonglong2 A67 = *reinterpret_cast<ulonglong2*>(&Asd[k][ty * 16 + 12]);
            ulonglong2 B01 = *reinterpret_cast<ulonglong2*>(&Bs[k][tx * 8 + 0]);
            ulonglong2 B23 = *reinterpret_cast<ulonglong2*>(&Bs[k][tx * 8 + 4]);
            ull ad[8] = {A01.x, A01.y, A23.x, A23.y, A45.x, A45.y, A67.x, A67.y};
            ull bp[4] = {B01.x, B01.y, B23.x, B23.y};
#pragma unroll
            for (int i = 0; i < 8; i++)
#pragma unroll
                for (int j = 0; j < 4; j++) FMA2(acc[i][j], ad[i], bp[j]);
        }
        __syncthreads();
    }

#pragma unroll
    for (int i = 0; i < 8; i++) {
        float* Crow = &g_xu[(size_t)(m0 + ty * 8 + i) * 256 + n0 + tx * 8];
        float v0, v1, v2, v3, v4, v5, v6, v7;
        UNPK(v0, v1, acc[i][0]);
        UNPK(v2, v3, acc[i][1]);
        UNPK(v4, v5, acc[i][2]);
        UNPK(v6, v7, acc[i][3]);
        *reinterpret_cast<float4*>(Crow + 0) = make_float4(v0, v1, v2, v3);
        *reinterpret_cast<float4*>(Crow + 4) = make_float4(v4, v5, v6, v7);
    }
}

// ---------------------------------------------------------------------------
// Phase 2: persistent batch-parallel recurrence. 128 CTAs x 2 batch rows,
// 512 threads (16 warps) for latency hiding.
// Thread (c = tid&127, q = tid>>7): cols {2c,2c+1}, K-quarter q: k in
// [64q, 64q+64). First 32 k-rows of each quarter live in smem (128 rows,
// 128KB); last 32 live in registers (wt[32] = 64 regs -> NO SPILL).
// h double-buffered in smem as {h0,h0,h1,h1} float4 per k (splat-ready,
// zero pack instructions).
// ---------------------------------------------------------------------------
__global__ __launch_bounds__(512, 1) void rnn_scan(const float* __restrict__ Wg,
                                                   const float* __restrict__ bg,
                                                   float* __restrict__ out) {
    extern __shared__ float smem[];
    float*      Ws   = smem;                                      // 128*256 f (128KB)
    float4*     hb4  = reinterpret_cast<float4*>(smem + 32768);   // 2 x 256 float4 (8KB)
    ulonglong2* redu = reinterpret_cast<ulonglong2*>(smem + 32768 + 2048); // 3*128 (6KB)

    const int tid = threadIdx.x;
    const int c   = tid & 127;
    const int cc  = 2 * c;
    const int q   = tid >> 7;   // K-quarter 0..3
    const int b0  = blockIdx.x * 2;
    const int b1  = b0 + 1;

    // smem W: dest row dr = 32*qq + j  <-  src k = 64*qq + j   (j in [0,32))
    for (int i = tid; i < 128 * 64; i += 512) {
        int dr = i >> 6;
        int cw = (i & 63) << 2;
        int sr = ((dr >> 5) << 6) + (dr & 31);  // 64*(dr/32) + dr%32
        *reinterpret_cast<float4*>(&Ws[dr * 256 + cw]) =
            *reinterpret_cast<const float4*>(&Wg[(size_t)sr * 256 + cw]);
    }
    // register-resident W tail: k in [64q+32, 64q+64), cols {cc, cc+1}
    ull wt[32];
    {
        const int kb = 64 * q + 32;
#pragma unroll
        for (int j = 0; j < 32; j++)
            wt[j] = *reinterpret_cast<const ull*>(&Wg[(size_t)(kb + j) * 256 + cc]);
    }
    // zero both h buffers
    for (int i = tid; i < 512; i += 512) hb4[i] = make_float4(0.f, 0.f, 0.f, 0.f);

    float2 bc   = make_float2(0.f, 0.f);
    float2 cur0 = make_float2(0.f, 0.f), cur1 = make_float2(0.f, 0.f);
    const float* xp0 = &g_xu[((size_t)b0 * TT) * 256 + cc];
    const float* xp1 = &g_xu[((size_t)b1 * TT) * 256 + cc];
    if (q == 0) {
        bc   = *reinterpret_cast<const float2*>(&bg[cc]);
        cur0 = *reinterpret_cast<const float2*>(xp0);
        cur1 = *reinterpret_cast<const float2*>(xp1);
    }
    __syncthreads();

    int rb = 0;
    const int wsbase = q * 32;  // smem W row base for this quarter
    for (int t = 0; t < TT; t++) {
        // prefetch next step's xu (overlaps the FMA chain)
        float2 nxt0 = cur0, nxt1 = cur1;
        if (q == 0 && t + 1 < TT) {
            nxt0 = *reinterpret_cast<const float2*>(xp0 + (size_t)(t + 1) * 256);
            nxt1 = *reinterpret_cast<const float2*>(xp1 + (size_t)(t + 1) * 256);
        }

        const ulonglong2* hp =
            reinterpret_cast<const ulonglong2*>(hb4 + rb * 256 + q * 64);
        ull a0 = 0ull, a1 = 0ull;
#pragma unroll 8
        for (int j = 0; j < 32; j++) {
            ulonglong2 h2 = hp[j];  // {h0,h0},{h1,h1} splats
            ull w = *reinterpret_cast<const ull*>(&Ws[(wsbase + j) * 256 + cc]);
            FMA2(a0, h2.x, w);
            FMA2(a1, h2.y, w);
        }
#pragma unroll 8
        for (int j = 0; j < 32; j++) {
            ulonglong2 h2 = hp[32 + j];
            FMA2(a0, h2.x, wt[j]);
            FMA2(a1, h2.y, wt[j]);
        }

        if (q != 0) redu[(q - 1) * 128 + c] = make_ulonglong2(a0, a1);
        __syncthreads();
        if (q == 0) {
            float s0x, s0y, s1x, s1y;
            UNPK(s0x, s0y, a0);
            UNPK(s1x, s1y, a1);
#pragma unroll
            for (int p = 0; p < 3; p++) {
                ulonglong2 r2 = redu[p * 128 + c];
                float t0x, t0y, t1x, t1y;
                UNPK(t0x, t0y, r2.x);
                UNPK(t1x, t1y, r2.y);
                s0x += t0x; s0y += t0y;
                s1x += t1x; s1y += t1y;
            }
            float r0x = tanhf(s0x + cur0.x + bc.x);
            float r0y = tanhf(s0y + cur0.y + bc.y);
            float r1x = tanhf(s1x + cur1.x + bc.x);
            float r1y = tanhf(s1y + cur1.y + bc.y);
            float4* hw = hb4 + (1 - rb) * 256;
            hw[cc]     = make_float4(r0x, r0x, r1x, r1x);
            hw[cc + 1] = make_float4(r0y, r0y, r1y, r1y);
        }
        __syncthreads();
        cur0 = nxt0;
        cur1 = nxt1;
        rb ^= 1;
    }

    // after 512 toggles rb==0; last write (t=511) went to buffer 0
    if (q == 0) {
        float4 p = hb4[rb * 256 + cc];      // {h0[2c],h0,h1[2c],h1}
        float4 r = hb4[rb * 256 + cc + 1];  // {h0[2c+1],...}
        *reinterpret_cast<float2*>(&out[(size_t)b0 * 256 + cc]) = make_float2(p.x, r.x);
        *reinterpret_cast<float2*>(&out[(size_t)b1 * 256 + cc]) = make_float2(p.z, r.z);
    }
}

extern "C" void kernel_launch(void* const* d_in, const int* in_sizes, int n_in,
                              void* d_out, int out_size) {
    const float* inputs = (const float*)d_in[0];  // [B,T,D]
    const float* U      = (const float*)d_in[1];  // [D,K]
    const float* W      = (const float*)d_in[2];  // [K,K]
    const float* b      = (const float*)d_in[3];  // [K]
    float* out          = (float*)d_out;          // [B,1,K]

    xu_gemm<<<2048, 256>>>(inputs, U);

    const int smem_bytes = 131072 + 8192 + 6144;  // W + h bufs + reduction
    cudaFuncSetAttribute(rnn_scan, cudaFuncAttributeMaxDynamicSharedMemorySize,
                         smem_bytes);
    rnn_scan<<<128, 512, smem_bytes>>>(W, b, out);
}

// round 7
// speedup vs baseline: 1.5039x; 1.2582x over previous
#include <cuda_runtime.h>
#include <math.h>

#define BB 256
#define TT 512
#define KK 256

typedef unsigned long long ull;

// scratch for xU [B*T, K] = 134MB (static device global: no runtime alloc)
__device__ float g_xu[(size_t)BB * TT * KK];

#define FMA2(d, a, b) \
    asm("fma.rn.f32x2 %0, %1, %2, %0;" : "+l"(d) : "l"(a), "l"(b))
#define UNPK(x, y, v) \
    asm("mov.b64 {%0, %1}, %2;" : "=f"(x), "=f"(y) : "l"(v))

__device__ __forceinline__ ull splat(float x) {
    ull r;
    asm("mov.b64 %0, {%1, %1};" : "=l"(r) : "f"(x));
    return r;
}

// ---------------------------------------------------------------------------
// Phase 1: C[m][n] = sum_d A[m][d] * U[d][n],  M=131072, N=K=256
// CTA tile 128x128, 256 threads, 8x8 microtile via packed f32x2.
// A tile duplicated in smem ({a,a} splats load as 64-bit words).
// B columns per thread: {tx*4..+3} and {64+tx*4..+3} -> B loads are 16
// CONSECUTIVE 16B lane-addresses = 2 wavefronts (was 4 with tx*8).
// ---------------------------------------------------------------------------
__global__ __launch_bounds__(256) void xu_gemm(const float* __restrict__ A,
                                               const float* __restrict__ U) {
    __shared__ float Asd[16][256];  // [k][2r],[2r+1] both hold A[m0+r][kc+k]
    __shared__ float Bs[16][128];   // [k][n]

    const int tid = threadIdx.x;
    const int m0 = (blockIdx.x >> 1) * 128;
    const int n0 = (blockIdx.x & 1) * 128;
    const int tx = tid & 15;   // cols tx*4..+3 and 64+tx*4..+3
    const int ty = tid >> 4;   // rows ty*8 .. +7

    ull acc[8][4];
#pragma unroll
    for (int i = 0; i < 8; i++)
#pragma unroll
        for (int j = 0; j < 4; j++) acc[i][j] = 0ull;

    for (int kc = 0; kc < 256; kc += 16) {
#pragma unroll
        for (int l = 0; l < 2; l++) {
            int idx = tid * 2 + l;        // 0..511
            int r   = idx >> 2;           // row 0..127
            int kq  = (idx & 3) * 4;      // k 0,4,8,12
            const float4 f = *reinterpret_cast<const float4*>(
                &A[(size_t)(m0 + r) * 256 + kc + kq]);
            *reinterpret_cast<float2*>(&Asd[kq + 0][2 * r]) = make_float2(f.x, f.x);
            *reinterpret_cast<float2*>(&Asd[kq + 1][2 * r]) = make_float2(f.y, f.y);
            *reinterpret_cast<float2*>(&Asd[kq + 2][2 * r]) = make_float2(f.z, f.z);
            *reinterpret_cast<float2*>(&Asd[kq + 3][2 * r]) = make_float2(f.w, f.w);
        }
#pragma unroll
        for (int l = 0; l < 2; l++) {
            int idx = tid * 2 + l;        // 0..511
            int r   = idx >> 5;           // 0..15
            int cg  = (idx & 31) * 4;
            *reinterpret_cast<float4*>(&Bs[r][cg]) =
                *reinterpret_cast<const float4*>(&U[(size_t)(kc + r) * 256 + n0 + cg]);
        }
        __syncthreads();

#pragma unroll
        for (int k = 0; k < 16; k++) {
            ulonglong2 A01 = *reinterpret_cast<ulonglong2*>(&Asd[k][ty * 16 + 0]);
            ulonglong2 A23 = *reinterpret_cast<ulonglong2*>(&Asd[k][ty * 16 + 4]);
            ulonglong2 A45 = *reinterpret_cast<ulonglong2*>(&Asd[k][ty * 16 + 8]);
            ulonglong2 A67 = *reinterpret_cast<ulonglong2*>(&Asd[k][ty * 16 + 12]);
            ulonglong2 B01 = *reinterpret_cast<ulonglong2*>(&Bs[k][tx * 4]);
            ulonglong2 B23 = *reinterpret_cast<ulonglong2*>(&Bs[k][64 + tx * 4]);
            ull ad[8] = {A01.x, A01.y, A23.x, A23.y, A45.x, A45.y, A67.x, A67.y};
            ull bp[4] = {B01.x, B01.y, B23.x, B23.y};
#pragma unroll
            for (int i = 0; i < 8; i++)
#pragma unroll
                for (int j = 0; j < 4; j++) FMA2(acc[i][j], ad[i], bp[j]);
        }
        __syncthreads();
    }

#pragma unroll
    for (int i = 0; i < 8; i++) {
        float* Crow = &g_xu[(size_t)(m0 + ty * 8 + i) * 256 + n0];
        float v0, v1, v2, v3, v4, v5, v6, v7;
        UNPK(v0, v1, acc[i][0]);
        UNPK(v2, v3, acc[i][1]);
        UNPK(v4, v5, acc[i][2]);
        UNPK(v6, v7, acc[i][3]);
        *reinterpret_cast<float4*>(Crow + tx * 4)      = make_float4(v0, v1, v2, v3);
        *reinterpret_cast<float4*>(Crow + 64 + tx * 4) = make_float4(v4, v5, v6, v7);
    }
}

// ---------------------------------------------------------------------------
// Phase 2: persistent batch-parallel recurrence. 128 CTAs x 2 batch rows,
// 512 threads (16 warps).
// Mainloop role (c = tid&127, q = tid>>7): cols {2c,2c+1}, k in [64q,64q+64).
//   k rows [64q,64q+32) from smem W (128KB); [64q+32,64q+64) from wt[32] regs.
// h stored NON-duplicated: float2 {h_b0[k], h_b1[k]} -> one float4 broadcast
//   covers 2 k for both rows (halves h crossbar traffic); splats rebuilt via
//   mov.b64 {x,x} (issue pipe has headroom).
// Epilogue role (col = tid&255, row = tid>>8): every thread reduces 4
//   partials, applies xu+b+tanh for ONE output element, writes h (and out).
// ---------------------------------------------------------------------------
__global__ __launch_bounds__(512, 1) void rnn_scan(const float* __restrict__ Wg,
                                                   const float* __restrict__ bg,
                                                   float* __restrict__ out) {
    extern __shared__ float smem[];
    float*      Ws   = smem;                                   // 128*256 f (128KB)
    float2*     hb2  = reinterpret_cast<float2*>(smem + 32768);   // 2 x 256 float2 (4KB)
    ulonglong2* redu = reinterpret_cast<ulonglong2*>(smem + 32768 + 1024); // 4*128 (8KB)

    const int tid = threadIdx.x;
    const int c   = tid & 127;
    const int cc  = 2 * c;
    const int q   = tid >> 7;        // K-quarter 0..3
    const int col = tid & 255;       // epilogue column
    const int row = tid >> 8;        // epilogue batch row (0/1)
    const int b0  = blockIdx.x * 2;

    // smem W: dest row dr = 32*qq + j  <-  src k = 64*qq + j   (j in [0,32))
    for (int i = tid; i < 128 * 64; i += 512) {
        int dr = i >> 6;
        int cw = (i & 63) << 2;
        int sr = ((dr >> 5) << 6) + (dr & 31);  // 64*(dr/32) + dr%32
        *reinterpret_cast<float4*>(&Ws[dr * 256 + cw]) =
            *reinterpret_cast<const float4*>(&Wg[(size_t)sr * 256 + cw]);
    }
    // register-resident W tail: k in [64q+32, 64q+64), cols {cc, cc+1}
    ull wt[32];
    {
        const int kb = 64 * q + 32;
#pragma unroll
        for (int j = 0; j < 32; j++)
            wt[j] = *reinterpret_cast<const ull*>(&Wg[(size_t)(kb + j) * 256 + cc]);
    }
    // zero both h buffers (512 float2 total, one per thread)
    hb2[tid] = make_float2(0.f, 0.f);

    const float  bcol = bg[col];
    const float* xp   = &g_xu[((size_t)(b0 + row) * TT) * 256 + col];
    float cur  = xp[0];
    float last = 0.f;
    __syncthreads();

    int rb = 0;
    const int wsbase = q * 32;  // smem W row base for this quarter
    for (int t = 0; t < TT; t++) {
        // prefetch next step's xu element (hidden under the FMA chain)
        float nxt = cur;
        if (t + 1 < TT) nxt = xp[(size_t)(t + 1) * 256];

        const float4* hq4 =
            reinterpret_cast<const float4*>(hb2 + rb * 256 + q * 64);
        ull a0 = 0ull, a1 = 0ull;
#pragma unroll 4
        for (int j2 = 0; j2 < 16; j2++) {   // k = 64q + 2*j2, +1 (smem W)
            float4 hv = hq4[j2];            // {h0[k],h1[k],h0[k+1],h1[k+1]}
            ull w0 = *reinterpret_cast<const ull*>(&Ws[(wsbase + 2 * j2) * 256 + cc]);
            ull w1 = *reinterpret_cast<const ull*>(&Ws[(wsbase + 2 * j2 + 1) * 256 + cc]);
            FMA2(a0, splat(hv.x), w0);
            FMA2(a1, splat(hv.y), w0);
            FMA2(a0, splat(hv.z), w1);
            FMA2(a1, splat(hv.w), w1);
        }
#pragma unroll 4
        for (int j2 = 0; j2 < 16; j2++) {   // k = 64q+32 + 2*j2, +1 (reg W)
            float4 hv = hq4[16 + j2];
            FMA2(a0, splat(hv.x), wt[2 * j2]);
            FMA2(a1, splat(hv.y), wt[2 * j2]);
            FMA2(a0, splat(hv.z), wt[2 * j2 + 1]);
            FMA2(a1, splat(hv.w), wt[2 * j2 + 1]);
        }
        // partials: floats [r0:cc, r0:cc+1, r1:cc, r1:cc+1]
        redu[q * 128 + c] = make_ulonglong2(a0, a1);
        __syncthreads();

        // epilogue: one output element per thread
        {
            const float* rf = reinterpret_cast<const float*>(redu);
            const int    fo = ((col >> 1) << 2) + row * 2 + (col & 1);
            float s = cur + bcol;
#pragma unroll
            for (int qq = 0; qq < 4; qq++) s += rf[qq * 512 + fo];
            last = tanhf(s);
            float* hw = reinterpret_cast<float*>(&hb2[(1 - rb) * 256 + col]);
            hw[row] = last;
        }
        __syncthreads();
        cur = nxt;
        rb ^= 1;
    }

    out[(size_t)(b0 + row) * 256 + col] = last;
}

extern "C" void kernel_launch(void* const* d_in, const int* in_sizes, int n_in,
                              void* d_out, int out_size) {
    const float* inputs = (const float*)d_in[0];  // [B,T,D]
    const float* U      = (const float*)d_in[1];  // [D,K]
    const float* W      = (const float*)d_in[2];  // [K,K]
    const float* b      = (const float*)d_in[3];  // [K]
    float* out          = (float*)d_out;          // [B,1,K]

    xu_gemm<<<2048, 256>>>(inputs, U);

    const int smem_bytes = 131072 + 4096 + 8192;  // W + h bufs + partials
    cudaFuncSetAttribute(rnn_scan, cudaFuncAttributeMaxDynamicSharedMemorySize,
                         smem_bytes);
    rnn_scan<<<128, 512, smem_bytes>>>(W, b, out);
}

// round 9
// speedup vs baseline: 2.0614x; 1.3707x over previous
#include <cuda_runtime.h>
#include <math.h>

#define BB 256
#define TT 512
#define KK 256

typedef unsigned long long ull;

// scratch for xU [B*T, K] = 134MB (static device global: no runtime alloc)
__device__ float g_xu[(size_t)BB * TT * KK];

#define FMA2(d, a, b) \
    asm("fma.rn.f32x2 %0, %1, %2, %0;" : "+l"(d) : "l"(a), "l"(b))
#define ADD2(d, s) \
    asm("add.rn.f32x2 %0, %0, %1;" : "+l"(d) : "l"(s))
#define UNPK(x, y, v) \
    asm("mov.b64 {%0, %1}, %2;" : "=f"(x), "=f"(y) : "l"(v))

__device__ __forceinline__ ull splat(float x) {
    ull r;
    asm("mov.b64 %0, {%1, %1};" : "=l"(r) : "f"(x));
    return r;
}

// ---------------------------------------------------------------------------
// Phase 1: C[m][n] = sum_d A[m][d] * U[d][n],  M=131072, N=K=256
// CTA tile 128x128, 256 threads, 8x8 microtile via packed f32x2.
// A tile duplicated in smem ({a,a} splats load as 64-bit words).
// ---------------------------------------------------------------------------
__global__ __launch_bounds__(256) void xu_gemm(const float* __restrict__ A,
                                               const float* __restrict__ U) {
    __shared__ float Asd[16][256];  // [k][2r],[2r+1] both hold A[m0+r][kc+k]
    __shared__ float Bs[16][128];   // [k][n]

    const int tid = threadIdx.x;
    const int m0 = (blockIdx.x >> 1) * 128;
    const int n0 = (blockIdx.x & 1) * 128;
    const int tx = tid & 15;   // cols tx*4..+3 and 64+tx*4..+3
    const int ty = tid >> 4;   // rows ty*8 .. +7

    ull acc[8][4];
#pragma unroll
    for (int i = 0; i < 8; i++)
#pragma unroll
        for (int j = 0; j < 4; j++) acc[i][j] = 0ull;

    for (int kc = 0; kc < 256; kc += 16) {
#pragma unroll
        for (int l = 0; l < 2; l++) {
            int idx = tid * 2 + l;        // 0..511
            int r   = idx >> 2;           // row 0..127
            int kq  = (idx & 3) * 4;      // k 0,4,8,12
            const float4 f = *reinterpret_cast<const float4*>(
                &A[(size_t)(m0 + r) * 256 + kc + kq]);
            *reinterpret_cast<float2*>(&Asd[kq + 0][2 * r]) = make_float2(f.x, f.x);
            *reinterpret_cast<float2*>(&Asd[kq + 1][2 * r]) = make_float2(f.y, f.y);
            *reinterpret_cast<float2*>(&Asd[kq + 2][2 * r]) = make_float2(f.z, f.z);
            *reinterpret_cast<float2*>(&Asd[kq + 3][2 * r]) = make_float2(f.w, f.w);
        }
#pragma unroll
        for (int l = 0; l < 2; l++) {
            int idx = tid * 2 + l;        // 0..511
            int r   = idx >> 5;           // 0..15
            int cg  = (idx & 31) * 4;
            *reinterpret_cast<float4*>(&Bs[r][cg]) =
                *reinterpret_cast<const float4*>(&U[(size_t)(kc + r) * 256 + n0 + cg]);
        }
        __syncthreads();

#pragma unroll
        for (int k = 0; k < 16; k++) {
            ulonglong2 A01 = *reinterpret_cast<ulonglong2*>(&Asd[k][ty * 16 + 0]);
            ulonglong2 A23 = *reinterpret_cast<ulonglong2*>(&Asd[k][ty * 16 + 4]);
            ulonglong2 A45 = *reinterpret_cast<ulonglong2*>(&Asd[k][ty * 16 + 8]);
            ulonglong2 A67 = *reinterpret_cast<ulonglong2*>(&Asd[k][ty * 16 + 12]);
            ulonglong2 B01 = *reinterpret_cast<ulonglong2*>(&Bs[k][tx * 4]);
            ulonglong2 B23 = *reinterpret_cast<ulonglong2*>(&Bs[k][64 + tx * 4]);
            ull ad[8] = {A01.x, A01.y, A23.x, A23.y, A45.x, A45.y, A67.x, A67.y};
            ull bp[4] = {B01.x, B01.y, B23.x, B23.y};
#pragma unroll
            for (int i = 0; i < 8; i++)
#pragma unroll
                for (int j = 0; j < 4; j++) FMA2(acc[i][j], ad[i], bp[j]);
        }
        __syncthreads();
    }

#pragma unroll
    for (int i = 0; i < 8; i++) {
        float* Crow = &g_xu[(size_t)(m0 + ty * 8 + i) * 256 + n0];
        float v0, v1, v2, v3, v4, v5, v6, v7;
        UNPK(v0, v1, acc[i][0]);
        UNPK(v2, v3, acc[i][1]);
        UNPK(v4, v5, acc[i][2]);
        UNPK(v6, v7, acc[i][3]);
        *reinterpret_cast<float4*>(Crow + tx * 4)      = make_float4(v0, v1, v2, v3);
        *reinterpret_cast<float4*>(Crow + 64 + tx * 4) = make_float4(v4, v5, v6, v7);
    }
}

// ---------------------------------------------------------------------------
// Phase 2: persistent batch-parallel recurrence. 128 CTAs x 2 batch rows,
// 512 threads.
// Mainloop (c = tid&127, q = tid>>7): cols {2c,2c+1}, k in [64q, 64q+64).
//   k-pairs [0,14) of the quarter (k rows [64q,64q+28)) come from smem W in
//   PAIRED layout: float4 {W[k][cc],W[k][cc+1],W[k+1][cc],W[k+1][cc+1]} so a
//   single LDS.128 feeds two k-steps. k rows [64q+28,64q+64) live in wt[36]
//   registers (72 regs).
// 4 accumulator chains (row x k-parity) merged with add.rn.f32x2.
// h stored non-duplicated: float2 {h_b0[k], h_b1[k]}; float4 read covers 2 k.
// Epilogue (col = tid&255, row = tid>>8): one output element per thread.
// ---------------------------------------------------------------------------
__global__ __launch_bounds__(512, 1) void rnn_scan(const float* __restrict__ Wg,
                                                   const float* __restrict__ bg,
                                                   float* __restrict__ out) {
    extern __shared__ float smem[];
    // Wp: 4 quarters * 14 k-pairs * 128 col-pairs of float4 = 112KB
    float4*     Wp   = reinterpret_cast<float4*>(smem);
    float2*     hb2  = reinterpret_cast<float2*>(smem + 28672);       // 4KB
    ulonglong2* redu = reinterpret_cast<ulonglong2*>(smem + 28672 + 1024); // 8KB

    const int tid = threadIdx.x;
    const int c   = tid & 127;
    const int cc  = 2 * c;
    const int q   = tid >> 7;        // K-quarter 0..3
    const int col = tid & 255;       // epilogue column
    const int row = tid >> 8;        // epilogue batch row (0/1)
    const int b0  = blockIdx.x * 2;

    // Build paired-k W smem: p = ((qq*14 + j2)*128 + c2)
    for (int p = tid; p < 4 * 14 * 128; p += 512) {
        int qq  = p / (14 * 128);
        int rem = p - qq * 14 * 128;
        int j2  = rem >> 7;
        int c2  = rem & 127;
        int k   = 64 * qq + 2 * j2;
        float2 w0 = *reinterpret_cast<const float2*>(&Wg[(size_t)k * 256 + 2 * c2]);
        float2 w1 = *reinterpret_cast<const float2*>(&Wg[(size_t)(k + 1) * 256 + 2 * c2]);
        Wp[p] = make_float4(w0.x, w0.y, w1.x, w1.y);
    }
    // register-resident W: k in [64q+28, 64q+64), cols {cc, cc+1}
    ull wt[36];
    {
        const int kb = 64 * q + 28;
#pragma unroll
        for (int j = 0; j < 36; j++)
            wt[j] = *reinterpret_cast<const ull*>(&Wg[(size_t)(kb + j) * 256 + cc]);
    }
    // zero both h buffers (512 float2, one per thread)
    hb2[tid] = make_float2(0.f, 0.f);

    const float  bcol = bg[col];
    const float* xp   = &g_xu[((size_t)(b0 + row) * TT) * 256 + col];
    float cur  = xp[0];
    float last = 0.f;
    __syncthreads();

    int rb = 0;
    const ulonglong2* wq =
        reinterpret_cast<const ulonglong2*>(Wp) + ((size_t)q * 14 * 128 + c);
    for (int t = 0; t < TT; t++) {
        // prefetch next step's xu element (hidden under the FMA chain)
        float nxt = cur;
        if (t + 1 < TT) nxt = xp[(size_t)(t + 1) * 256];

        const float4* hq4 =
            reinterpret_cast<const float4*>(hb2 + rb * 256 + q * 64);
        ull a0 = 0ull, a1 = 0ull, e0 = 0ull, e1 = 0ull;
#pragma unroll
        for (int j2 = 0; j2 < 14; j2++) {   // k = 64q+2j2, +1   (smem W, paired)
            float4     hv = hq4[j2];        // {h0[k],h1[k],h0[k+1],h1[k+1]}
            ulonglong2 wv = wq[(size_t)j2 * 128];  // {W[k][cc..], W[k+1][cc..]}
            FMA2(a0, splat(hv.x), wv.x);
            FMA2(a1, splat(hv.y), wv.x);
            FMA2(e0, splat(hv.z), wv.y);
            FMA2(e1, splat(hv.w), wv.y);
        }
#pragma unroll
        for (int j2 = 14; j2 < 32; j2++) {  // k = 64q+2j2, +1   (register W)
            float4 hv = hq4[j2];
            ull w0 = wt[2 * j2 - 28];
            ull w1 = wt[2 * j2 - 27];
            FMA2(a0, splat(hv.x), w0);
            FMA2(a1, splat(hv.y), w0);
            FMA2(e0, splat(hv.z), w1);
            FMA2(e1, splat(hv.w), w1);
        }
        ADD2(a0, e0);
        ADD2(a1, e1);
        // partials: floats [r0:cc, r0:cc+1, r1:cc, r1:cc+1]
        redu[q * 128 + c] = make_ulonglong2(a0, a1);
        __syncthreads();

        // epilogue: one output element per thread
        {
            const float* rf = reinterpret_cast<const float*>(redu);
            const int    fo = ((col >> 1) << 2) + row * 2 + (col & 1);
            float s = cur + bcol;
#pragma unroll
            for (int qq = 0; qq < 4; qq++) s += rf[qq * 512 + fo];
            last = tanhf(s);
            float* hw = reinterpret_cast<float*>(&hb2[(1 - rb) * 256 + col]);
            hw[row] = last;
        }
        __syncthreads();
        cur = nxt;
        rb ^= 1;
    }

    out[(size_t)(b0 + row) * 256 + col] = last;
}

extern "C" void kernel_launch(void* const* d_in, const int* in_sizes, int n_in,
                              void* d_out, int out_size) {
    const float* inputs = (const float*)d_in[0];  // [B,T,D]
    const float* U      = (const float*)d_in[1];  // [D,K]
    const float* W      = (const float*)d_in[2];  // [K,K]
    const float* b      = (const float*)d_in[3];  // [K]
    float* out          = (float*)d_out;          // [B,1,K]

    xu_gemm<<<2048, 256>>>(inputs, U);

    const int smem_bytes = 114688 + 4096 + 8192;  // paired W + h bufs + partials
    cudaFuncSetAttribute(rnn_scan, cudaFuncAttributeMaxDynamicSharedMemorySize,
                         smem_bytes);
    rnn_scan<<<128, 512, smem_bytes>>>(W, b, out);
}